// round 1
// baseline (speedup 1.0000x reference)
#include <cuda_runtime.h>

// Problem constants
#define N_TOK   2048          // 4*512 tokens
#define CBN     8             // codebook_num = 512/(2*32)
#define DIM     32
#define NROWS   16384         // N_TOK * CBN
#define KCODES  16384
#define NSPLIT  4
#define KCHUNK  (KCODES / NSPLIT)   // 4096
#define TS      128                 // codes per smem tile
#define BLK     128                 // threads (=rows) per score block

// Output layout: zhat [2048,256] | kl_loss [1] | indices [2048,8] (as float)
#define ZHAT_OFF 0
#define KL_OFF   524288
#define IDX_OFF  524289

// Scratch (device globals; no allocation allowed)
__device__ float g_w1[NROWS * DIM];        // 0.5*(1 - 1/var)
__device__ float g_w2[NROWS * DIM];        // mu / var
__device__ float g_pbest[NROWS * NSPLIT];
__device__ int   g_pidx [NROWS * NSPLIT];
__device__ float g_klpart[2048];

// ---------------------------------------------------------------------------
// Prep: per (row n, dim d) weights + deterministic KL block partials.
// n = t*8 + cb ; d -> z column j = d*8 + cb ; mu = z[t][j], logvar = z[t][256+j]
// ---------------------------------------------------------------------------
__global__ void __launch_bounds__(256) prep_kernel(const float* __restrict__ z) {
    int idx = blockIdx.x * 256 + threadIdx.x;     // 0 .. 524287  (= n*32 + d)
    int n = idx >> 5;
    int d = idx & 31;
    int t  = n >> 3;
    int cb = n & 7;
    int j  = d * CBN + cb;

    float mu = z[t * 512 + j];
    float lv = z[t * 512 + 256 + j];
    lv = fminf(fmaxf(lv, -30.0f), 20.0f);
    float var = expf(lv);                 // matches reference var = exp(logvar)
    float sd  = expf(0.5f * lv);
    float inv = 1.0f / (sd * sd);         // matches reference inv_var = 1/std^2

    g_w1[idx] = 0.5f * (1.0f - inv);      // folds -0.5/var c^2 and +0.5 c^2 prior
    g_w2[idx] = mu * inv;

    float klt = mu * mu + var - 1.0f - lv;

    // deterministic block tree reduction
    __shared__ float sred[256];
    sred[threadIdx.x] = klt;
    __syncthreads();
    #pragma unroll
    for (int s = 128; s > 0; s >>= 1) {
        if (threadIdx.x < s) sred[threadIdx.x] += sred[threadIdx.x + s];
        __syncthreads();
    }
    if (threadIdx.x == 0) g_klpart[blockIdx.x] = sred[0];
}

// ---------------------------------------------------------------------------
// Score: each thread owns one row; block covers 128 rows x one K-chunk.
// Codebook tiles staged in smem (broadcast reads), w1/w2 in registers.
// score = sum_d c*(w1*c + w2)   -> 2 FMA per dim
// ---------------------------------------------------------------------------
__global__ void __launch_bounds__(BLK, 4) score_kernel(const float* __restrict__ codebook) {
    __shared__ __align__(16) float sc[TS * DIM];

    int row   = blockIdx.x * BLK + threadIdx.x;
    int chunk = blockIdx.y;
    int kbase = chunk * KCHUNK;

    float w1[DIM], w2[DIM];
    {
        const float4* w1v = (const float4*)(g_w1 + row * DIM);
        const float4* w2v = (const float4*)(g_w2 + row * DIM);
        #pragma unroll
        for (int q = 0; q < 8; ++q) {
            ((float4*)w1)[q] = w1v[q];
            ((float4*)w2)[q] = w2v[q];
        }
    }

    float best = -INFINITY;
    int   bidx = 0;

    for (int tb = 0; tb < KCHUNK / TS; ++tb) {
        __syncthreads();   // previous tile fully consumed
        {
            const float4* src = (const float4*)(codebook + (size_t)(kbase + tb * TS) * DIM);
            float4* dst = (float4*)sc;
            #pragma unroll
            for (int i = 0; i < (TS * DIM / 4) / BLK; ++i)   // 8 iters
                dst[threadIdx.x + i * BLK] = src[threadIdx.x + i * BLK];
        }
        __syncthreads();

        int gk0 = kbase + tb * TS;
        #pragma unroll 2
        for (int j = 0; j < TS; ++j) {
            const float4* cv4 = (const float4*)(sc + j * DIM);
            float a0 = 0.0f, a1 = 0.0f;
            #pragma unroll
            for (int q = 0; q < 8; ++q) {
                float4 cv = cv4[q];
                a0 = fmaf(fmaf(w1[q * 4 + 0], cv.x, w2[q * 4 + 0]), cv.x, a0);
                a1 = fmaf(fmaf(w1[q * 4 + 1], cv.y, w2[q * 4 + 1]), cv.y, a1);
                a0 = fmaf(fmaf(w1[q * 4 + 2], cv.z, w2[q * 4 + 2]), cv.z, a0);
                a1 = fmaf(fmaf(w1[q * 4 + 3], cv.w, w2[q * 4 + 3]), cv.w, a1);
            }
            float v = a0 + a1;
            if (v > best) { best = v; bidx = gk0 + j; }   // strict > keeps first max
        }
    }

    g_pbest[row * NSPLIT + chunk] = best;
    g_pidx [row * NSPLIT + chunk] = bidx;
}

// ---------------------------------------------------------------------------
// Finalize: merge chunk argmaxes (first-index tie-break), gather zhat with
// the [cb,dim]->[dim,cb] transpose, write indices, reduce KL.
// ---------------------------------------------------------------------------
__global__ void __launch_bounds__(256) finalize_kernel(const float* __restrict__ codebook,
                                                       float* __restrict__ out) {
    int n = blockIdx.x * 256 + threadIdx.x;   // 0 .. 16383

    float best = -INFINITY;
    int   bi   = 0;
    #pragma unroll
    for (int c = 0; c < NSPLIT; ++c) {        // ascending k-chunks: strict > = first max
        float v = g_pbest[n * NSPLIT + c];
        if (v > best) { best = v; bi = g_pidx[n * NSPLIT + c]; }
    }

    out[IDX_OFF + n] = (float)bi;

    int t  = n >> 3;
    int cb = n & 7;
    const float4* crow = (const float4*)(codebook + (size_t)bi * DIM);
    #pragma unroll
    for (int q = 0; q < 8; ++q) {
        float4 cv = crow[q];
        int d = q * 4;
        out[ZHAT_OFF + t * 256 + (d + 0) * CBN + cb] = cv.x;
        out[ZHAT_OFF + t * 256 + (d + 1) * CBN + cb] = cv.y;
        out[ZHAT_OFF + t * 256 + (d + 2) * CBN + cb] = cv.z;
        out[ZHAT_OFF + t * 256 + (d + 3) * CBN + cb] = cv.w;
    }

    // Deterministic KL final reduce in block 0
    if (blockIdx.x == 0) {
        __shared__ float s[256];
        float acc = 0.0f;
        #pragma unroll
        for (int i = 0; i < 8; ++i) acc += g_klpart[threadIdx.x * 8 + i];
        s[threadIdx.x] = acc;
        __syncthreads();
        #pragma unroll
        for (int st = 128; st > 0; st >>= 1) {
            if (threadIdx.x < st) s[threadIdx.x] += s[threadIdx.x + st];
            __syncthreads();
        }
        if (threadIdx.x == 0)
            out[KL_OFF] = (float)((double)s[0] * (1.4426 * 0.5 / 16384.0));
    }
}

// ---------------------------------------------------------------------------
extern "C" void kernel_launch(void* const* d_in, const int* in_sizes, int n_in,
                              void* d_out, int out_size) {
    const float* z        = (const float*)d_in[0];   // [4,512,512]
    // d_in[1] = noise: dead (STE makes zhat == zhat_v in forward value)
    const float* codebook = (const float*)d_in[2];   // [16384,32]
    float* out = (float*)d_out;

    prep_kernel<<<2048, 256>>>(z);
    score_kernel<<<dim3(NROWS / BLK, NSPLIT), BLK>>>(codebook);
    finalize_kernel<<<NROWS / 256, 256>>>(codebook, out);
}

// round 2
// speedup vs baseline: 1.4129x; 1.4129x over previous
#include <cuda_runtime.h>

typedef unsigned long long ull;

// Problem constants
#define N_TOK   2048
#define CBN     8
#define DIM     32
#define NROWS   16384         // N_TOK * CBN
#define KCODES  16384
#define NSPLIT  32
#define KCHUNK  (KCODES / NSPLIT)   // 512
#define TS      128                 // codes per smem tile
#define BLK     128                 // threads (=rows) per score block

// Output layout: zhat [2048,256] | kl_loss [1] | indices [2048,8] (as float)
#define ZHAT_OFF 0
#define KL_OFF   524288
#define IDX_OFF  524289

// Scratch
__device__ float g_w1[NROWS * DIM];        // 0.5*(1 - 1/var)
__device__ float g_w2[NROWS * DIM];        // mu / var
__device__ float g_pbest[NROWS * NSPLIT];
__device__ int   g_pidx [NROWS * NSPLIT];
__device__ float g_klpart[2048];

// Packed fp32x2 ops (Blackwell f32x2 SIMD — 2 FMA per fma-pipe instr)
#define FMA2(d, a, b, c) \
    asm("fma.rn.f32x2 %0, %1, %2, %3;" : "=l"(d) : "l"(a), "l"(b), "l"(c))
#define ADD2(d, a, b) \
    asm("add.rn.f32x2 %0, %1, %2;" : "=l"(d) : "l"(a), "l"(b))
#define UNPACK2(lo, hi, v) \
    asm("mov.b64 {%0, %1}, %2;" : "=f"(lo), "=f"(hi) : "l"(v))

// ---------------------------------------------------------------------------
// Prep: per (row n, dim d) weights + deterministic KL block partials.
// ---------------------------------------------------------------------------
__global__ void __launch_bounds__(256) prep_kernel(const float* __restrict__ z) {
    int idx = blockIdx.x * 256 + threadIdx.x;     // 0 .. 524287  (= n*32 + d)
    int n = idx >> 5;
    int d = idx & 31;
    int t  = n >> 3;
    int cb = n & 7;
    int j  = d * CBN + cb;

    float mu = z[t * 512 + j];
    float lv = z[t * 512 + 256 + j];
    lv = fminf(fmaxf(lv, -30.0f), 20.0f);
    float var = expf(lv);
    float sd  = expf(0.5f * lv);
    float inv = 1.0f / (sd * sd);

    g_w1[idx] = 0.5f * (1.0f - inv);
    g_w2[idx] = mu * inv;

    float klt = mu * mu + var - 1.0f - lv;

    __shared__ float sred[256];
    sred[threadIdx.x] = klt;
    __syncthreads();
    #pragma unroll
    for (int s = 128; s > 0; s >>= 1) {
        if (threadIdx.x < s) sred[threadIdx.x] += sred[threadIdx.x + s];
        __syncthreads();
    }
    if (threadIdx.x == 0) g_klpart[blockIdx.x] = sred[0];
}

// ---------------------------------------------------------------------------
// Score: 1 thread per row, block = 128 rows x one 512-code K chunk.
// Packed f32x2: dims paired into 64-bit lanes. 32 FFMA2 per code.
//   score = sum_d c*(w1*c + w2)
// ---------------------------------------------------------------------------
__global__ void __launch_bounds__(BLK, 4) score_kernel(const float* __restrict__ codebook) {
    __shared__ __align__(16) float sc[TS * DIM];   // 16KB

    int row   = blockIdx.x * BLK + threadIdx.x;
    int chunk = blockIdx.y;
    int kbase = chunk * KCHUNK;

    // Weights packed as (dim 2q, dim 2q+1) pairs — already adjacent in memory.
    ull w1p[16], w2p[16];
    {
        const ulonglong2* w1v = (const ulonglong2*)(g_w1 + (size_t)row * DIM);
        const ulonglong2* w2v = (const ulonglong2*)(g_w2 + (size_t)row * DIM);
        #pragma unroll
        for (int q = 0; q < 8; ++q) {
            ulonglong2 a = w1v[q];
            ulonglong2 b = w2v[q];
            w1p[2 * q]     = a.x;  w1p[2 * q + 1] = a.y;
            w2p[2 * q]     = b.x;  w2p[2 * q + 1] = b.y;
        }
    }

    float best = -INFINITY;
    int   bidx = 0;

    for (int tb = 0; tb < KCHUNK / TS; ++tb) {     // 4 tiles
        __syncthreads();
        {
            const float4* src = (const float4*)(codebook + (size_t)(kbase + tb * TS) * DIM);
            float4* dst = (float4*)sc;
            #pragma unroll
            for (int i = 0; i < (TS * DIM / 4) / BLK; ++i)   // 8 iters
                dst[threadIdx.x + i * BLK] = src[threadIdx.x + i * BLK];
        }
        __syncthreads();

        int gk0 = kbase + tb * TS;
        #pragma unroll 2
        for (int j = 0; j < TS; ++j) {
            const ulonglong2* cv = (const ulonglong2*)(sc + j * DIM);
            ull a0 = 0ULL, a1 = 0ULL;   // bit pattern 0 == (0.0f, 0.0f)
            #pragma unroll
            for (int q = 0; q < 8; ++q) {
                ulonglong2 cd = cv[q];
                ull t0, t1;
                FMA2(t0, w1p[2 * q],     cd.x, w2p[2 * q]);
                FMA2(a0, t0,             cd.x, a0);
                FMA2(t1, w1p[2 * q + 1], cd.y, w2p[2 * q + 1]);
                FMA2(a1, t1,             cd.y, a1);
            }
            ADD2(a0, a0, a1);
            float s0, s1;
            UNPACK2(s0, s1, a0);
            float v = s0 + s1;
            if (v > best) { best = v; bidx = gk0 + j; }   // strict > keeps first max
        }
    }

    g_pbest[row * NSPLIT + chunk] = best;
    g_pidx [row * NSPLIT + chunk] = bidx;
}

// ---------------------------------------------------------------------------
// Finalize: merge chunk argmaxes (ascending chunks, strict > = first index),
// gather zhat with [cb,dim]->[dim,cb] transpose, write indices, reduce KL.
// ---------------------------------------------------------------------------
__global__ void __launch_bounds__(256) finalize_kernel(const float* __restrict__ codebook,
                                                       float* __restrict__ out) {
    int n = blockIdx.x * 256 + threadIdx.x;   // 0 .. 16383

    float best = -INFINITY;
    int   bi   = 0;
    #pragma unroll
    for (int c = 0; c < NSPLIT; ++c) {
        float v = g_pbest[n * NSPLIT + c];
        if (v > best) { best = v; bi = g_pidx[n * NSPLIT + c]; }
    }

    out[IDX_OFF + n] = (float)bi;

    int t  = n >> 3;
    int cb = n & 7;
    const float4* crow = (const float4*)(codebook + (size_t)bi * DIM);
    #pragma unroll
    for (int q = 0; q < 8; ++q) {
        float4 cv = crow[q];
        int d = q * 4;
        out[ZHAT_OFF + t * 256 + (d + 0) * CBN + cb] = cv.x;
        out[ZHAT_OFF + t * 256 + (d + 1) * CBN + cb] = cv.y;
        out[ZHAT_OFF + t * 256 + (d + 2) * CBN + cb] = cv.z;
        out[ZHAT_OFF + t * 256 + (d + 3) * CBN + cb] = cv.w;
    }

    if (blockIdx.x == 0) {
        __shared__ float s[256];
        float acc = 0.0f;
        #pragma unroll
        for (int i = 0; i < 8; ++i) acc += g_klpart[threadIdx.x * 8 + i];
        s[threadIdx.x] = acc;
        __syncthreads();
        #pragma unroll
        for (int st = 128; st > 0; st >>= 1) {
            if (threadIdx.x < st) s[threadIdx.x] += s[threadIdx.x + st];
            __syncthreads();
        }
        if (threadIdx.x == 0)
            out[KL_OFF] = (float)((double)s[0] * (1.4426 * 0.5 / 16384.0));
    }
}

// ---------------------------------------------------------------------------
extern "C" void kernel_launch(void* const* d_in, const int* in_sizes, int n_in,
                              void* d_out, int out_size) {
    const float* z        = (const float*)d_in[0];   // [4,512,512]
    // d_in[1] = noise: dead in forward value (STE)
    const float* codebook = (const float*)d_in[2];   // [16384,32]
    float* out = (float*)d_out;

    prep_kernel<<<2048, 256>>>(z);
    score_kernel<<<dim3(NROWS / BLK, NSPLIT), BLK>>>(codebook);
    finalize_kernel<<<NROWS / 256, 256>>>(codebook, out);
}

// round 4
// speedup vs baseline: 2.6662x; 1.8870x over previous
#include <cuda_runtime.h>
#include <cuda_bf16.h>
#include <cstdint>

// ---------------------------------------------------------------- constants
#define N_TOK   2048
#define CBN     8
#define DIM     32
#define NROWS   16384
#define KCODES  16384
#define FEAT    64                 // [w1|w2] / [c^2|c]
#define MTILES  (NROWS / 16)       // 1024 m16 tiles
#define NTILES  (KCODES / 8)       // 2048 n8 tiles
#define NSPLIT  8
#define TPS     (NTILES / NSPLIT)  // 256 n-tiles per split
#define NCAND   64                 // candidates per row (8 splits x 4 thr x 2)

// Output layout: zhat [2048,256] | kl_loss [1] | indices [2048,8] (as float)
#define ZHAT_OFF 0
#define KL_OFF   524288
#define IDX_OFF  524289

// ---------------------------------------------------------------- scratch
__device__ float g_w1[NROWS * DIM];          // 0.5*(1 - 1/var)
__device__ float g_w2[NROWS * DIM];          // mu / var
__device__ uint4 g_Afrag[MTILES * 4 * 2 * 32];   // [mt][kstep][plane][lane] a0..a3
__device__ uint4 g_Bfrag[(size_t)NTILES * 4 * 32]; // [nt][kstep][lane] {bh0,bh1,bl0,bl1}
__device__ float g_cv[(size_t)NROWS * NCAND];
__device__ int   g_ci[(size_t)NROWS * NCAND];
__device__ float g_klpart[2048];

// ---------------------------------------------------------------- helpers
__device__ __forceinline__ uint32_t bpack(float x, float y) {
    unsigned short ux = __bfloat16_as_ushort(__float2bfloat16_rn(x));
    unsigned short uy = __bfloat16_as_ushort(__float2bfloat16_rn(y));
    return (uint32_t)ux | ((uint32_t)uy << 16);
}
__device__ __forceinline__ float bhi(float x) {
    return __bfloat162float(__float2bfloat16_rn(x));
}

__device__ __forceinline__ void mma_bf16(float& d0, float& d1, float& d2, float& d3,
                                         uint4 a, uint32_t b0, uint32_t b1) {
    asm volatile("mma.sync.aligned.m16n8k16.row.col.f32.bf16.bf16.f32 "
        "{%0,%1,%2,%3}, {%4,%5,%6,%7}, {%8,%9}, {%0,%1,%2,%3};"
        : "+f"(d0), "+f"(d1), "+f"(d2), "+f"(d3)
        : "r"(a.x), "r"(a.y), "r"(a.z), "r"(a.w), "r"(b0), "r"(b1));
}

__device__ __forceinline__ void upd2(float v, int idx,
                                     float& v1, int& i1, float& v2, int& i2) {
    if (v > v2) {
        if (v > v1) { v2 = v1; i2 = i1; v1 = v; i1 = idx; }
        else        { v2 = v;  i2 = idx; }
    }
}

// ---------------------------------------------------------------- prep: weights + KL
__global__ void __launch_bounds__(256) prep_kernel(const float* __restrict__ z) {
    int idx = blockIdx.x * 256 + threadIdx.x;     // n*32 + d
    int n = idx >> 5;
    int d = idx & 31;
    int t  = n >> 3;
    int cb = n & 7;
    int j  = d * CBN + cb;

    float mu = z[t * 512 + j];
    float lv = z[t * 512 + 256 + j];
    lv = fminf(fmaxf(lv, -30.0f), 20.0f);
    float var = expf(lv);
    float sd  = expf(0.5f * lv);
    float inv = 1.0f / (sd * sd);

    g_w1[idx] = 0.5f * (1.0f - inv);
    g_w2[idx] = mu * inv;

    float klt = mu * mu + var - 1.0f - lv;
    __shared__ float sred[256];
    sred[threadIdx.x] = klt;
    __syncthreads();
    #pragma unroll
    for (int s = 128; s > 0; s >>= 1) {
        if (threadIdx.x < s) sred[threadIdx.x] += sred[threadIdx.x + s];
        __syncthreads();
    }
    if (threadIdx.x == 0) g_klpart[blockIdx.x] = sred[0];
}

// ---------------------------------------------------------------- A fragments
// m16n8k16 A row-major frag: a0:(r, k0,k0+1) a1:(r+8, k0,k0+1) a2:(r, k0+8,k0+9) a3:(r+8, ...)
// with r = lane/4, k0 = (lane%4)*2.  feat f<32 -> w1[f], else w2[f-32].
__device__ __forceinline__ float getw(int row, int f) {
    return (f < 32) ? g_w1[row * 32 + f] : g_w2[row * 32 + (f - 32)];
}

__global__ void __launch_bounds__(256) build_afrag() {
    int idx = blockIdx.x * 256 + threadIdx.x;     // 131072 threads
    int lane = idx & 31;
    int ks   = (idx >> 5) & 3;
    int mt   = idx >> 7;

    int r0 = mt * 16 + (lane >> 2);
    int r1 = r0 + 8;
    int k0 = ks * 16 + (lane & 3) * 2;

    float x0 = getw(r0, k0),     x1 = getw(r0, k0 + 1);
    float x2 = getw(r1, k0),     x3 = getw(r1, k0 + 1);
    float x4 = getw(r0, k0 + 8), x5 = getw(r0, k0 + 9);
    float x6 = getw(r1, k0 + 8), x7 = getw(r1, k0 + 9);

    uint4 hi, lo;
    hi.x = bpack(bhi(x0), bhi(x1));  lo.x = bpack(x0 - bhi(x0), x1 - bhi(x1));
    hi.y = bpack(bhi(x2), bhi(x3));  lo.y = bpack(x2 - bhi(x2), x3 - bhi(x3));
    hi.z = bpack(bhi(x4), bhi(x5));  lo.z = bpack(x4 - bhi(x4), x5 - bhi(x5));
    hi.w = bpack(bhi(x6), bhi(x7));  lo.w = bpack(x6 - bhi(x6), x7 - bhi(x7));

    g_Afrag[((mt * 4 + ks) * 2 + 0) * 32 + lane] = hi;
    g_Afrag[((mt * 4 + ks) * 2 + 1) * 32 + lane] = lo;
}

// ---------------------------------------------------------------- B fragments
// m16n8k16 B col-major frag: b0:(k0,k0+1 ; n) b1:(k0+8,k0+9 ; n), n = lane/4, k0=(lane%4)*2.
// feat f<32 -> c[f]^2, else c[f-32].
__global__ void __launch_bounds__(256) build_bfrag(const float* __restrict__ codebook) {
    int idx = blockIdx.x * 256 + threadIdx.x;     // 262144 threads
    int lane = idx & 31;
    int ks   = (idx >> 5) & 3;
    int nt   = idx >> 7;

    int n  = nt * 8 + (lane >> 2);
    int k0 = ks * 16 + (lane & 3) * 2;
    const float* cr = codebook + (size_t)n * 32;

    float y0, y1, y2, y3;
    {
        int f = k0;
        float a = (f < 32) ? cr[f] * cr[f] : cr[f - 32];
        float b = (f + 1 < 32) ? cr[f + 1] * cr[f + 1] : cr[f + 1 - 32];
        y0 = a; y1 = b;
        f = k0 + 8;
        float c2 = (f < 32) ? cr[f] * cr[f] : cr[f - 32];
        float d2 = (f + 1 < 32) ? cr[f + 1] * cr[f + 1] : cr[f + 1 - 32];
        y2 = c2; y3 = d2;
    }

    uint4 v;
    v.x = bpack(bhi(y0), bhi(y1));                 // b0 hi
    v.y = bpack(bhi(y2), bhi(y3));                 // b1 hi
    v.z = bpack(y0 - bhi(y0), y1 - bhi(y1));       // b0 lo
    v.w = bpack(y2 - bhi(y2), y3 - bhi(y3));       // b1 lo

    g_Bfrag[((size_t)nt * 4 + ks) * 32 + lane] = v;
}

// ---------------------------------------------------------------- score (mma.sync bf16)
// Block 256 thr = 8 warps; warp owns one m16 tile; grid (128 M-blocks, 8 N-splits).
// 3 passes (hi*hi + hi*lo + lo*hi) fused per k-step.
__global__ void __launch_bounds__(256) score_mma() {
    int warp = threadIdx.x >> 5;
    int lane = threadIdx.x & 31;
    int mt   = blockIdx.x * 8 + warp;

    uint4 ahi[4], alo[4];
    #pragma unroll
    for (int ks = 0; ks < 4; ++ks) {
        ahi[ks] = g_Afrag[((mt * 4 + ks) * 2 + 0) * 32 + lane];
        alo[ks] = g_Afrag[((mt * 4 + ks) * 2 + 1) * 32 + lane];
    }

    float v1a = -INFINITY, v2a = -INFINITY, v1b = -INFINITY, v2b = -INFINITY;
    int   i1a = 0, i2a = 0, i1b = 0, i2b = 0;

    int t0 = blockIdx.y * TPS;
    #pragma unroll 2
    for (int t = 0; t < TPS; ++t) {
        const uint4* bp = g_Bfrag + ((size_t)(t0 + t) * 4) * 32 + lane;
        uint4 b0 = bp[0];
        uint4 b1 = bp[32];
        uint4 b2 = bp[64];
        uint4 b3 = bp[96];

        float d0 = 0.f, d1 = 0.f, d2 = 0.f, d3 = 0.f;
        mma_bf16(d0, d1, d2, d3, ahi[0], b0.x, b0.y);
        mma_bf16(d0, d1, d2, d3, ahi[0], b0.z, b0.w);
        mma_bf16(d0, d1, d2, d3, alo[0], b0.x, b0.y);
        mma_bf16(d0, d1, d2, d3, ahi[1], b1.x, b1.y);
        mma_bf16(d0, d1, d2, d3, ahi[1], b1.z, b1.w);
        mma_bf16(d0, d1, d2, d3, alo[1], b1.x, b1.y);
        mma_bf16(d0, d1, d2, d3, ahi[2], b2.x, b2.y);
        mma_bf16(d0, d1, d2, d3, ahi[2], b2.z, b2.w);
        mma_bf16(d0, d1, d2, d3, alo[2], b2.x, b2.y);
        mma_bf16(d0, d1, d2, d3, ahi[3], b3.x, b3.y);
        mma_bf16(d0, d1, d2, d3, ahi[3], b3.z, b3.w);
        mma_bf16(d0, d1, d2, d3, alo[3], b3.x, b3.y);

        int col = (t0 + t) * 8 + (lane & 3) * 2;
        upd2(d0, col,     v1a, i1a, v2a, i2a);
        upd2(d1, col + 1, v1a, i1a, v2a, i2a);
        upd2(d2, col,     v1b, i1b, v2b, i2b);
        upd2(d3, col + 1, v1b, i1b, v2b, i2b);
    }

    int rowA = mt * 16 + (lane >> 2);
    int rowB = rowA + 8;
    int cbase = blockIdx.y * 8 + (lane & 3) * 2;
    g_cv[(size_t)rowA * NCAND + cbase]     = v1a;  g_ci[(size_t)rowA * NCAND + cbase]     = i1a;
    g_cv[(size_t)rowA * NCAND + cbase + 1] = v2a;  g_ci[(size_t)rowA * NCAND + cbase + 1] = i2a;
    g_cv[(size_t)rowB * NCAND + cbase]     = v1b;  g_ci[(size_t)rowB * NCAND + cbase]     = i1b;
    g_cv[(size_t)rowB * NCAND + cbase + 1] = v2b;  g_ci[(size_t)rowB * NCAND + cbase + 1] = i2b;
}

// ---------------------------------------------------------------- finalize
// Warp per row: rescore 64 candidates exactly in fp32, argmax (min-index ties),
// gather zhat with the [cb,dim]->[dim,cb] transpose, write index; block 0 does KL.
__global__ void __launch_bounds__(256) finalize_kernel(const float* __restrict__ codebook,
                                                       float* __restrict__ out) {
    int warp = threadIdx.x >> 5;
    int lane = threadIdx.x & 31;
    int n = blockIdx.x * 8 + warp;     // 0..16383

    // warp-uniform weight row (broadcast loads)
    float w1r[DIM], w2r[DIM];
    {
        const float4* a = (const float4*)(g_w1 + (size_t)n * DIM);
        const float4* b = (const float4*)(g_w2 + (size_t)n * DIM);
        #pragma unroll
        for (int q = 0; q < 8; ++q) {
            ((float4*)w1r)[q] = a[q];
            ((float4*)w2r)[q] = b[q];
        }
    }

    float bv = -INFINITY;
    int   bi = 0x7FFFFFFF;
    #pragma unroll
    for (int e = 0; e < 2; ++e) {
        int ci = g_ci[(size_t)n * NCAND + lane + e * 32];
        const float4* cr = (const float4*)(codebook + (size_t)ci * DIM);
        float a0 = 0.f, a1 = 0.f;
        #pragma unroll
        for (int q = 0; q < 8; ++q) {
            float4 cv = cr[q];
            int d = q * 4;
            a0 = fmaf(w1r[d],     cv.x * cv.x, a0);  a0 = fmaf(w2r[d],     cv.x, a0);
            a1 = fmaf(w1r[d + 1], cv.y * cv.y, a1);  a1 = fmaf(w2r[d + 1], cv.y, a1);
            a0 = fmaf(w1r[d + 2], cv.z * cv.z, a0);  a0 = fmaf(w2r[d + 2], cv.z, a0);
            a1 = fmaf(w1r[d + 3], cv.w * cv.w, a1);  a1 = fmaf(w2r[d + 3], cv.w, a1);
        }
        float s = a0 + a1;
        if (s > bv || (s == bv && ci < bi)) { bv = s; bi = ci; }
    }
    // butterfly argmax (min index on exact ties)
    #pragma unroll
    for (int off = 16; off > 0; off >>= 1) {
        float ov = __shfl_xor_sync(0xFFFFFFFF, bv, off);
        int   oi = __shfl_xor_sync(0xFFFFFFFF, bi, off);
        if (ov > bv || (ov == bv && oi < bi)) { bv = ov; bi = oi; }
    }

    int t  = n >> 3;
    int cb = n & 7;
    // zhat gather: lane = dim d; out[t*256 + d*8 + cb]
    float cval = codebook[(size_t)bi * DIM + lane];
    out[ZHAT_OFF + t * 256 + lane * CBN + cb] = cval;
    if (lane == 0) out[IDX_OFF + n] = (float)bi;

    // KL final reduce in block 0 (all 256 threads participate)
    if (blockIdx.x == 0) {
        __shared__ float s[256];
        float acc = 0.0f;
        #pragma unroll
        for (int i = 0; i < 8; ++i) acc += g_klpart[threadIdx.x * 8 + i];
        s[threadIdx.x] = acc;
        __syncthreads();
        #pragma unroll
        for (int st = 128; st > 0; st >>= 1) {
            if (threadIdx.x < st) s[threadIdx.x] += s[threadIdx.x + st];
            __syncthreads();
        }
        if (threadIdx.x == 0)
            out[KL_OFF] = (float)((double)s[0] * (1.4426 * 0.5 / 16384.0));
    }
}

// ----------------------------------------------------------------
extern "C" void kernel_launch(void* const* d_in, const int* in_sizes, int n_in,
                              void* d_out, int out_size) {
    const float* z        = (const float*)d_in[0];   // [4,512,512]
    // d_in[1] = noise: dead in forward value (STE)
    const float* codebook = (const float*)d_in[2];   // [16384,32]
    float* out = (float*)d_out;

    prep_kernel<<<2048, 256>>>(z);
    build_afrag<<<512, 256>>>();
    build_bfrag<<<1024, 256>>>(codebook);
    score_mma<<<dim3(MTILES / 8, NSPLIT), 256>>>();
    finalize_kernel<<<NROWS / 8, 256>>>(codebook, out);
}